// round 11
// baseline (speedup 1.0000x reference)
#include <cuda_runtime.h>
#include <cuda_fp16.h>
#include <cstdint>

#define NBS   256
#define NNOD  128
#define NDIM  64
#define NC    64
#define NK    32
#define CKTOT (NC*NK)

#define A2f 0.0225421101f     // log2(e)/64
#define C2f 0.0450842203f     // 2*log2(e)/64
#define S1f 0.21233045f       // sqrt(C2f): scale inputs so MMA acc = C2*dot

// ---------------- smem layout (byte offsets from 1KB-aligned base) ----------
#define OFF_XHI   0                     // 128x64 fp16 SW128 (16KB)
#define OFF_AT(b) (16384 + (b)*16384)   // 4 atom chunk bufs (fp16, 16KB each)
#define OFF_XNL   81920                 // float[128]
#define OFF_RED   82432                 // float[33]
#define SMEM_DYN  (82944 + 1024)

// pre-converted atoms: scaled fp16, already in SW128 tile byte order
static __device__ uint16_t g_at_h[CKTOT * NDIM];
static __device__ float    g_anL[CKTOT];   // A2*||atom_ck||^2
static __device__ float    g_kyy[NC];

// ---------------------------------------------------------------------------
__device__ __forceinline__ uint32_t smem_u32(const void* p) {
    uint32_t a;
    asm("{ .reg .u64 t; cvta.to.shared.u64 t, %1; cvt.u32.u64 %0, t; }" : "=r"(a) : "l"(p));
    return a;
}
__device__ __forceinline__ uint32_t sw128(uint32_t o) { return o ^ ((o >> 3) & 0x70); }

__device__ __forceinline__ void ldsm4(uint32_t r[4], uint32_t addr) {
    asm volatile("ldmatrix.sync.aligned.m8n8.x4.shared.b16 {%0,%1,%2,%3}, [%4];"
                 : "=r"(r[0]), "=r"(r[1]), "=r"(r[2]), "=r"(r[3]) : "r"(addr));
}
__device__ __forceinline__ void mma16816(float c[4], const uint32_t a[4], const uint32_t b[2]) {
    asm volatile("mma.sync.aligned.m16n8k16.row.col.f32.f16.f16.f32 "
                 "{%0,%1,%2,%3}, {%4,%5,%6,%7}, {%8,%9}, {%0,%1,%2,%3};"
                 : "+f"(c[0]), "+f"(c[1]), "+f"(c[2]), "+f"(c[3])
                 : "r"(a[0]), "r"(a[1]), "r"(a[2]), "r"(a[3]), "r"(b[0]), "r"(b[1]));
}
__device__ __forceinline__ void cp16(uint32_t dst, const void* src) {
    asm volatile("cp.async.cg.shared.global [%0], [%1], 16;" :: "r"(dst), "l"(src) : "memory");
}
#define CP_COMMIT() asm volatile("cp.async.commit_group;" ::: "memory")
#define CP_WAIT1()  asm volatile("cp.async.wait_group 1;" ::: "memory")

// MUFU exp2 (fp32 — f16x2 variant failed the 1e-3 gate in R6)
__device__ __forceinline__ float mexp2(float x) {
    float r;
    asm("ex2.approx.f32 %0, %1;" : "=f"(r) : "f"(x));
    return r;
}
// FMA-pipe exp2 for the (tiny) prep kernel
__device__ __forceinline__ float fexp2(float x) {
    float r = x + 12582912.0f;
    int   m = __float_as_int(r);
    float t = x - (r - 12582912.0f);
    float p =            1.3333558e-3f;
    p = fmaf(p, t, 9.6181291e-3f);
    p = fmaf(p, t, 5.5504109e-2f);
    p = fmaf(p, t, 2.4022651e-1f);
    p = fmaf(p, t, 6.9314718e-1f);
    p = fmaf(p, t, 1.0f);
    return __int_as_float(__float_as_int(p) + (m << 23));
}
__device__ __forceinline__ float wred(float v) {
#pragma unroll
    for (int o = 16; o; o >>= 1) v += __shfl_xor_sync(0xffffffffu, v, o);
    return v;
}

// ---------------------------------------------------------------------------
// Prep: per-ck-row scaled norms, k_yy, fp16 atoms in pre-swizzled layout
// ---------------------------------------------------------------------------
__global__ void mmd_prep(const float* __restrict__ atoms)
{
    __shared__ float at[NK][NDIM + 4];
    __shared__ float anl[NK];
    __shared__ float ssum;
    const int c = blockIdx.x, tid = threadIdx.x;

    const float4* ag = (const float4*)(atoms + (size_t)c * NK * NDIM);
#pragma unroll
    for (int t = 0; t < 4; ++t) {
        int idx = t * 128 + tid;
        int row = idx >> 4, k4 = idx & 15;
        *(float4*)&at[row][k4 * 4] = ag[idx];
    }
    if (tid == 0) ssum = 0.0f;
    __syncthreads();

    if (tid < NK) {
        float s = 0.0f;
#pragma unroll
        for (int k = 0; k < NDIM; k += 4) {
            float4 v = *(const float4*)&at[tid][k];
            s = fmaf(v.x, v.x, fmaf(v.y, v.y, fmaf(v.z, v.z, fmaf(v.w, v.w, s))));
        }
        anl[tid] = s;
        g_anL[c * NK + tid] = s * A2f;
    }
    __syncthreads();

#pragma unroll
    for (int t = 0; t < 16; ++t) {
        int idx = t * 128 + tid;            // 0..2047
        int r = idx >> 6, k = idx & 63;
        float v = at[r][k] * S1f;
        int gr = c * NK + r;
        int chunk = gr >> 7, rin = gr & 127;
        uint32_t off = sw128((uint32_t)(rin * 128 + k * 2));
        g_at_h[(uint32_t)chunk * 8192u + (off >> 1)] =
            __half_as_ushort(__float2half_rn(v));
    }

    float ps = 0.0f;
#pragma unroll
    for (int t = 0; t < 8; ++t) {
        int p = t * 128 + tid;
        int i = p >> 5, j = p & 31;
        float dot = 0.0f;
#pragma unroll
        for (int k = 0; k < NDIM; k += 4) {
            float4 a  = *(const float4*)&at[i][k];
            float4 bb = *(const float4*)&at[j][k];
            dot = fmaf(a.x, bb.x, fmaf(a.y, bb.y, fmaf(a.z, bb.z, fmaf(a.w, bb.w, dot))));
        }
        ps += fexp2(fmaf(dot, C2f, -A2f * (anl[i] + anl[j])));
    }
    ps = wred(ps);
    if ((tid & 31) == 0) atomicAdd(&ssum, ps);
    __syncthreads();
    if (tid == 0) g_kyy[c] = ssum * (1.0f / (NK * NK));
}

// ---------------------------------------------------------------------------
// One 128x128 chunk, warp tile 64x32 (ks-outer, R7 form):
// MMA (norms folded into acc init) + fp32 ex2 epilogue.
// ---------------------------------------------------------------------------
__device__ __forceinline__ float chunk_sum(
    uint32_t Ahi, uint32_t Bb,
    uint32_t aRow, uint32_t bRow, uint32_t klowA, uint32_t klowB, uint32_t mask,
    const float nxr[8], const float cn[8])
{
    float c[4][4][4];
#pragma unroll
    for (int mt = 0; mt < 4; ++mt)
#pragma unroll
        for (int nt = 0; nt < 4; ++nt) {
            c[mt][nt][0] = nxr[mt * 2 + 0] - cn[nt * 2 + 0];
            c[mt][nt][1] = nxr[mt * 2 + 0] - cn[nt * 2 + 1];
            c[mt][nt][2] = nxr[mt * 2 + 1] - cn[nt * 2 + 0];
            c[mt][nt][3] = nxr[mt * 2 + 1] - cn[nt * 2 + 1];
        }

#pragma unroll
    for (int ks = 0; ks < 4; ++ks) {
        const uint32_t colA = ((uint32_t)(ks * 32) + klowA) ^ mask;
        const uint32_t colB = ((uint32_t)(ks * 32) + klowB) ^ mask;
        uint32_t b0[4], b1[4];
        ldsm4(b0, Bb + bRow + colB);            // cols wn*32 .. +15
        ldsm4(b1, Bb + bRow + 2048 + colB);     // cols +16 .. +31
#pragma unroll
        for (int mt = 0; mt < 4; ++mt) {
            uint32_t a[4];
            ldsm4(a, Ahi + aRow + mt * 2048 + colA);
            mma16816(c[mt][0], a, b0 + 0);
            mma16816(c[mt][1], a, b0 + 2);
            mma16816(c[mt][2], a, b1 + 0);
            mma16816(c[mt][3], a, b1 + 2);
        }
    }

    float s0 = 0.f, s1 = 0.f, s2 = 0.f, s3 = 0.f;
#pragma unroll
    for (int mt = 0; mt < 4; ++mt)
#pragma unroll
        for (int nt = 0; nt < 4; ++nt) {
            s0 += mexp2(c[mt][nt][0]);
            s1 += mexp2(c[mt][nt][1]);
            s2 += mexp2(c[mt][nt][2]);
            s3 += mexp2(c[mt][nt][3]);
        }
    return (s0 + s1) + (s2 + s3);
}

// ---------------------------------------------------------------------------
// Main: TWO CTAs per graph (atom halves). CTA (b,h): kxx + chunks h*8..h*8+7,
// writes out[b, h*32..h*32+31]. No cross-CTA communication.
// ---------------------------------------------------------------------------
__global__ void __launch_bounds__(256, 2)
mmd_main(const float* __restrict__ x, float* __restrict__ out)
{
    extern __shared__ char sraw[];
    char* sm = (char*)(((uintptr_t)sraw + 1023) & ~(uintptr_t)1023);
    const uint32_t sb = smem_u32(sm);

    float* xnL = (float*)(sm + OFF_XNL);
    float* red = (float*)(sm + OFF_RED);

    const int tid = threadIdx.x, wid = tid >> 5, l = tid & 31;
    const int b    = blockIdx.x >> 1;
    const int half = blockIdx.x & 1;
    const int base = half * 8;            // first atom chunk for this CTA
    const int wm = wid >> 2;              // row half    -> rows wm*64..+63
    const int wn = wid & 3;               // col quarter -> one atom

    if (tid < 33) red[tid] = 0.0f;

    // ---- prefetch local chunks 0,1 (= global base, base+1; contiguous 32KB) ----
    {
        const uint4* g = (const uint4*)g_at_h + (size_t)base * 1024;
        uint32_t d = sb + OFF_AT(0);
#pragma unroll
        for (int t = 0; t < 8; ++t) {
            int i = t * 256 + tid;
            cp16(d + i * 16, g + i);
        }
        CP_COMMIT();
    }

    // ---- x tile: scaled fp16 into SW128 smem ----
    const float4* xg = (const float4*)(x + (size_t)b * NNOD * NDIM);
#pragma unroll
    for (int t = 0; t < 8; ++t) {
        int idx = t * 256 + tid;               // 0..2047 float4
        int row = idx >> 4, k4 = idx & 15;
        float4 v = xg[idx];
        __half h0 = __float2half_rn(v.x * S1f), h1 = __float2half_rn(v.y * S1f);
        __half h2 = __float2half_rn(v.z * S1f), h3 = __float2half_rn(v.w * S1f);
        uint32_t off = sw128((uint32_t)(row * 128 + k4 * 8));
        uint2 ph;
        ph.x = (uint32_t)__half_as_ushort(h0) | ((uint32_t)__half_as_ushort(h1) << 16);
        ph.y = (uint32_t)__half_as_ushort(h2) | ((uint32_t)__half_as_ushort(h3) << 16);
        *(uint2*)(sm + OFF_XHI + off) = ph;
    }
    if (tid < NNOD) {
        const float4* xr4 = (const float4*)(x + ((size_t)b * NNOD + tid) * NDIM);
        float s = 0.0f;
#pragma unroll
        for (int k = 0; k < 16; ++k) {
            float4 v = xr4[k];
            s = fmaf(v.x, v.x, fmaf(v.y, v.y, fmaf(v.z, v.z, fmaf(v.w, v.w, s))));
        }
        xnL[tid] = s * A2f;
    }
    __syncthreads();

    // ---- per-thread ldmatrix address components ----
    const uint32_t mask  = (uint32_t)((l & 7) << 4);
    const uint32_t aRow  = (uint32_t)((wm * 64 + (l & 7) + ((l >> 3) & 1) * 8) * 128);
    const uint32_t klowA = (uint32_t)(((l >> 4) & 1) * 16);
    const uint32_t bRow  = (uint32_t)((wn * 32 + (l & 7) + ((l >> 4) & 1) * 8) * 128);
    const uint32_t klowB = (uint32_t)(((l >> 3) & 1) * 16);
    const uint32_t Ahi   = sb + OFF_XHI;

    // negated row norms: rows wm*64 + mt*16 + (l>>2) + r*8
    float nxr[8];
#pragma unroll
    for (int mt = 0; mt < 4; ++mt) {
        nxr[mt * 2 + 0] = -xnL[wm * 64 + mt * 16 + (l >> 2)];
        nxr[mt * 2 + 1] = -xnL[wm * 64 + mt * 16 + (l >> 2) + 8];
    }

    // ---- k_xx chunk first (B = x tile; overlaps the initial prefetch) ----
    {
        float cn[8];
#pragma unroll
        for (int nt = 0; nt < 4; ++nt) {
            cn[nt * 2 + 0] = xnL[wn * 32 + nt * 8 + (l & 3) * 2];
            cn[nt * 2 + 1] = xnL[wn * 32 + nt * 8 + (l & 3) * 2 + 1];
        }
        float s = wred(chunk_sum(Ahi, Ahi, aRow, bRow, klowA, klowB, mask, nxr, cn));
        if (l == 0) atomicAdd(&red[32], s);
    }

    // ---- 4 pairs of atom chunks (local lch = 2p+h, global ch = base+lch) ----
#pragma unroll 1
    for (int p = 0; p < 4; ++p) {
        __syncthreads();                         // prior pair's reads complete
        if (p < 3) {                             // prefetch local chunks 2p+2,2p+3
            const uint4* g = (const uint4*)g_at_h + (size_t)(base + 2 * p + 2) * 1024;
            uint32_t d = sb + OFF_AT((2 * p + 2) & 3);   // contiguous 32KB pair
#pragma unroll
            for (int t = 0; t < 8; ++t) {
                int i = t * 256 + tid;
                cp16(d + i * 16, g + i);
            }
        }
        CP_COMMIT();
        CP_WAIT1();                              // local chunks 2p, 2p+1 landed
        __syncthreads();

#pragma unroll
        for (int h = 0; h < 2; ++h) {
            const int lch = 2 * p + h;
            const int ch  = base + lch;
            float cn[8];
#pragma unroll
            for (int nt = 0; nt < 4; ++nt) {
                cn[nt * 2 + 0] = __ldg(&g_anL[ch * 128 + wn * 32 + nt * 8 + (l & 3) * 2]);
                cn[nt * 2 + 1] = __ldg(&g_anL[ch * 128 + wn * 32 + nt * 8 + (l & 3) * 2 + 1]);
            }
            float s = wred(chunk_sum(Ahi, sb + OFF_AT(lch & 3),
                                     aRow, bRow, klowA, klowB, mask, nxr, cn));
            if (l == 0) atomicAdd(&red[lch * 4 + wn], s);
        }
    }

    __syncthreads();
    if (tid < 32) {
        const int c = half * 32 + tid;           // global atom index
        float kxy = red[tid] * (1.0f / (NNOD * NK));
        float kxx = red[32]  * (1.0f / (NNOD * NNOD));
        out[b * NC + c] = kxx + g_kyy[c] - 2.0f * kxy;
    }
}

// ---------------------------------------------------------------------------
extern "C" void kernel_launch(void* const* d_in, const int* in_sizes, int n_in,
                              void* d_out, int out_size)
{
    const float* x     = (const float*)d_in[0];
    const float* atoms = (const float*)d_in[1];
    if (n_in >= 2 && in_sizes[0] == CKTOT * NDIM && in_sizes[1] == NBS * NNOD * NDIM) {
        x     = (const float*)d_in[1];
        atoms = (const float*)d_in[0];
    }
    float* out = (float*)d_out;

    cudaFuncSetAttribute(mmd_main, cudaFuncAttributeMaxDynamicSharedMemorySize, SMEM_DYN);

    mmd_prep<<<NC, 128>>>(atoms);
    mmd_main<<<2 * NBS, 256, SMEM_DYN>>>(x, out);
}

// round 13
// speedup vs baseline: 1.0006x; 1.0006x over previous
#include <cuda_runtime.h>
#include <cuda_fp16.h>
#include <cstdint>

#define NBS   256
#define NNOD  128
#define NDIM  64
#define NC    64
#define NK    32
#define CKTOT (NC*NK)

#define A2f 0.0225421101f     // log2(e)/64
#define C2f 0.0450842203f     // 2*log2(e)/64
#define S1f 0.21233045f       // sqrt(C2f): scale inputs so MMA acc = C2*dot

// ---------------- smem layout (byte offsets from 1KB-aligned base) ----------
#define OFF_XHI   0                     // 128x64 fp16 SW128 (16KB)
#define OFF_AT(b) (16384 + (b)*16384)   // 4 atom chunk bufs (fp16, 16KB each)
#define OFF_XNL   81920                 // float[128]
#define OFF_RED   82432                 // float[65]
#define SMEM_DYN  (82944 + 1024)

// pre-converted atoms: scaled fp16, already in SW128 tile byte order
static __device__ uint16_t g_at_h[CKTOT * NDIM];
static __device__ float    g_anL[CKTOT];    // A2*||atom_ck||^2
static __device__ float    g_kyy4[4 * NC];  // per-quarter kyy partial sums

// ---------------------------------------------------------------------------
__device__ __forceinline__ uint32_t smem_u32(const void* p) {
    uint32_t a;
    asm("{ .reg .u64 t; cvta.to.shared.u64 t, %1; cvt.u32.u64 %0, t; }" : "=r"(a) : "l"(p));
    return a;
}
__device__ __forceinline__ uint32_t sw128(uint32_t o) { return o ^ ((o >> 3) & 0x70); }

__device__ __forceinline__ void ldsm4(uint32_t r[4], uint32_t addr) {
    asm volatile("ldmatrix.sync.aligned.m8n8.x4.shared.b16 {%0,%1,%2,%3}, [%4];"
                 : "=r"(r[0]), "=r"(r[1]), "=r"(r[2]), "=r"(r[3]) : "r"(addr));
}
__device__ __forceinline__ void mma16816(float c[4], const uint32_t a[4], const uint32_t b[2]) {
    asm volatile("mma.sync.aligned.m16n8k16.row.col.f32.f16.f16.f32 "
                 "{%0,%1,%2,%3}, {%4,%5,%6,%7}, {%8,%9}, {%0,%1,%2,%3};"
                 : "+f"(c[0]), "+f"(c[1]), "+f"(c[2]), "+f"(c[3])
                 : "r"(a[0]), "r"(a[1]), "r"(a[2]), "r"(a[3]), "r"(b[0]), "r"(b[1]));
}
__device__ __forceinline__ void cp16(uint32_t dst, const void* src) {
    asm volatile("cp.async.cg.shared.global [%0], [%1], 16;" :: "r"(dst), "l"(src) : "memory");
}
#define CP_COMMIT() asm volatile("cp.async.commit_group;" ::: "memory")
#define CP_WAIT1()  asm volatile("cp.async.wait_group 1;" ::: "memory")

// MUFU exp2 (fp32 only — ALL fp16 exp paths failed the 1e-3 gate: R6, R12)
__device__ __forceinline__ float mexp2(float x) {
    float r;
    asm("ex2.approx.f32 %0, %1;" : "=f"(r) : "f"(x));
    return r;
}
// FMA-pipe exp2, deg-5, ~3e-7 rel accuracy on [-16,0]
__device__ __forceinline__ float fexp2(float x) {
    float r = x + 12582912.0f;
    int   m = __float_as_int(r);
    float t = x - (r - 12582912.0f);
    float p =            1.3333558e-3f;
    p = fmaf(p, t, 9.6181291e-3f);
    p = fmaf(p, t, 5.5504109e-2f);
    p = fmaf(p, t, 2.4022651e-1f);
    p = fmaf(p, t, 6.9314718e-1f);
    p = fmaf(p, t, 1.0f);
    return __int_as_float(__float_as_int(p) + (m << 23));
}
__device__ __forceinline__ float wred(float v) {
#pragma unroll
    for (int o = 16; o; o >>= 1) v += __shfl_xor_sync(0xffffffffu, v, o);
    return v;
}

// ---------------------------------------------------------------------------
// Prep, grid 320:
//   blocks 0..63   : atom conversion (fp16, pre-swizzled) + scaled norms
//   blocks 64..319 : k_yy quarters — block handles 256 pairs of one atom
// ---------------------------------------------------------------------------
__global__ void mmd_prep(const float* __restrict__ atoms)
{
    const int bid = blockIdx.x, tid = threadIdx.x;

    if (bid < NC) {
        // ---- conversion + norms for atom c = bid ----
        const int c = bid;
        if (tid < NK) {
            const float4* ar = (const float4*)(atoms + (size_t)(c * NK + tid) * NDIM);
            float s = 0.0f;
#pragma unroll
            for (int k = 0; k < 16; ++k) {
                float4 v = ar[k];
                s = fmaf(v.x, v.x, fmaf(v.y, v.y, fmaf(v.z, v.z, fmaf(v.w, v.w, s))));
            }
            g_anL[c * NK + tid] = s * A2f;
        }
#pragma unroll
        for (int t = 0; t < 16; ++t) {
            int idx = t * 128 + tid;            // 0..2047
            int r = idx >> 6, k = idx & 63;
            float v = atoms[(size_t)(c * NK + r) * NDIM + k] * S1f;
            int gr = c * NK + r;
            int chunk = gr >> 7, rin = gr & 127;
            uint32_t off = sw128((uint32_t)(rin * 128 + k * 2));
            g_at_h[(uint32_t)chunk * 8192u + (off >> 1)] =
                __half_as_ushort(__float2half_rn(v));
        }
    } else {
        // ---- k_yy quarter q of atom c: pairs [q*256, q*256+256) ----
        __shared__ float ssum;
        const int q = (bid - NC) >> 6, c = (bid - NC) & 63;
        if (tid == 0) ssum = 0.0f;
        __syncthreads();

        float ps = 0.0f;
#pragma unroll
        for (int t = 0; t < 2; ++t) {
            const int p = q * 256 + t * 128 + tid;
            const int i = p >> 5, j = p & 31;
            const float4* ra = (const float4*)(atoms + (size_t)(c * NK + i) * NDIM);
            const float4* rb = (const float4*)(atoms + (size_t)(c * NK + j) * NDIM);
            float dot = 0.f, na = 0.f, nb = 0.f;
#pragma unroll
            for (int k = 0; k < 16; ++k) {
                float4 a  = ra[k];
                float4 bb = rb[k];
                dot = fmaf(a.x, bb.x, fmaf(a.y, bb.y, fmaf(a.z, bb.z, fmaf(a.w, bb.w, dot))));
                na  = fmaf(a.x, a.x,  fmaf(a.y, a.y,  fmaf(a.z, a.z,  fmaf(a.w, a.w,  na))));
                nb  = fmaf(bb.x, bb.x, fmaf(bb.y, bb.y, fmaf(bb.z, bb.z, fmaf(bb.w, bb.w, nb))));
            }
            ps += fexp2(fmaf(dot, C2f, -A2f * (na + nb)));
        }
        ps = wred(ps);
        if ((tid & 31) == 0) atomicAdd(&ssum, ps);
        __syncthreads();
        if (tid == 0) g_kyy4[q * NC + c] = ssum;
    }
}

// ---------------------------------------------------------------------------
// One 128x128 chunk, warp tile 64x32 (ks-outer, R7 form):
// MMA (norms folded into acc init) + mixed MUFU/FMA fp32 exp2 epilogue
// (3 of 4 exps on MUFU, 1 of 4 on the FMA pipe — pipe balancing).
// ---------------------------------------------------------------------------
__device__ __forceinline__ float chunk_sum(
    uint32_t Ahi, uint32_t Bb,
    uint32_t aRow, uint32_t bRow, uint32_t klowA, uint32_t klowB, uint32_t mask,
    const float nxr[8], const float cn[8])
{
    float c[4][4][4];
#pragma unroll
    for (int mt = 0; mt < 4; ++mt)
#pragma unroll
        for (int nt = 0; nt < 4; ++nt) {
            c[mt][nt][0] = nxr[mt * 2 + 0] - cn[nt * 2 + 0];
            c[mt][nt][1] = nxr[mt * 2 + 0] - cn[nt * 2 + 1];
            c[mt][nt][2] = nxr[mt * 2 + 1] - cn[nt * 2 + 0];
            c[mt][nt][3] = nxr[mt * 2 + 1] - cn[nt * 2 + 1];
        }

#pragma unroll
    for (int ks = 0; ks < 4; ++ks) {
        const uint32_t colA = ((uint32_t)(ks * 32) + klowA) ^ mask;
        const uint32_t colB = ((uint32_t)(ks * 32) + klowB) ^ mask;
        uint32_t b0[4], b1[4];
        ldsm4(b0, Bb + bRow + colB);            // cols wn*32 .. +15
        ldsm4(b1, Bb + bRow + 2048 + colB);     // cols +16 .. +31
#pragma unroll
        for (int mt = 0; mt < 4; ++mt) {
            uint32_t a[4];
            ldsm4(a, Ahi + aRow + mt * 2048 + colA);
            mma16816(c[mt][0], a, b0 + 0);
            mma16816(c[mt][1], a, b0 + 2);
            mma16816(c[mt][2], a, b1 + 0);
            mma16816(c[mt][3], a, b1 + 2);
        }
    }

    // epilogue: fp32 exps, 3/4 on MUFU + 1/4 on the FMA pipe
    float s0 = 0.f, s1 = 0.f, s2 = 0.f, s3 = 0.f;
#pragma unroll
    for (int mt = 0; mt < 4; ++mt)
#pragma unroll
        for (int nt = 0; nt < 4; ++nt) {
            s0 += mexp2(c[mt][nt][0]);
            s1 += mexp2(c[mt][nt][1]);
            s2 += mexp2(c[mt][nt][2]);
            s3 += fexp2(c[mt][nt][3]);
        }
    return (s0 + s1) + (s2 + s3);
}

// ---------------------------------------------------------------------------
// Main: one CTA per graph; kxx first (overlaps prefetch), then 8 chunk-pairs.
// ---------------------------------------------------------------------------
__global__ void __launch_bounds__(256, 2)
mmd_main(const float* __restrict__ x, float* __restrict__ out)
{
    extern __shared__ char sraw[];
    char* sm = (char*)(((uintptr_t)sraw + 1023) & ~(uintptr_t)1023);
    const uint32_t sb = smem_u32(sm);

    float* xnL = (float*)(sm + OFF_XNL);
    float* red = (float*)(sm + OFF_RED);

    const int tid = threadIdx.x, wid = tid >> 5, l = tid & 31;
    const int b  = blockIdx.x;
    const int wm = wid >> 2;      // row half    -> rows wm*64..+63
    const int wn = wid & 3;       // col quarter -> cols wn*32..+31 = one atom

    if (tid < 65) red[tid] = 0.0f;

    // ---- prefetch chunks 0,1 into bufs 0,1 (one contiguous 32KB group) ----
    {
        const uint4* g = (const uint4*)g_at_h;
        uint32_t d = sb + OFF_AT(0);
#pragma unroll
        for (int t = 0; t < 8; ++t) {
            int i = t * 256 + tid;
            cp16(d + i * 16, g + i);
        }
        CP_COMMIT();
    }

    // ---- x tile: scaled fp16 into SW128 smem ----
    const float4* xg = (const float4*)(x + (size_t)b * NNOD * NDIM);
#pragma unroll
    for (int t = 0; t < 8; ++t) {
        int idx = t * 256 + tid;               // 0..2047 float4
        int row = idx >> 4, k4 = idx & 15;
        float4 v = xg[idx];
        __half h0 = __float2half_rn(v.x * S1f), h1 = __float2half_rn(v.y * S1f);
        __half h2 = __float2half_rn(v.z * S1f), h3 = __float2half_rn(v.w * S1f);
        uint32_t off = sw128((uint32_t)(row * 128 + k4 * 8));
        uint2 ph;
        ph.x = (uint32_t)__half_as_ushort(h0) | ((uint32_t)__half_as_ushort(h1) << 16);
        ph.y = (uint32_t)__half_as_ushort(h2) | ((uint32_t)__half_as_ushort(h3) << 16);
        *(uint2*)(sm + OFF_XHI + off) = ph;
    }
    if (tid < NNOD) {
        const float4* xr4 = (const float4*)(x + ((size_t)b * NNOD + tid) * NDIM);
        float s = 0.0f;
#pragma unroll
        for (int k = 0; k < 16; ++k) {
            float4 v = xr4[k];
            s = fmaf(v.x, v.x, fmaf(v.y, v.y, fmaf(v.z, v.z, fmaf(v.w, v.w, s))));
        }
        xnL[tid] = s * A2f;
    }
    __syncthreads();

    // ---- per-thread ldmatrix address components ----
    const uint32_t mask  = (uint32_t)((l & 7) << 4);
    const uint32_t aRow  = (uint32_t)((wm * 64 + (l & 7) + ((l >> 3) & 1) * 8) * 128);
    const uint32_t klowA = (uint32_t)(((l >> 4) & 1) * 16);
    const uint32_t bRow  = (uint32_t)((wn * 32 + (l & 7) + ((l >> 4) & 1) * 8) * 128);
    const uint32_t klowB = (uint32_t)(((l >> 3) & 1) * 16);
    const uint32_t Ahi   = sb + OFF_XHI;

    // negated row norms: rows wm*64 + mt*16 + (l>>2) + r*8
    float nxr[8];
#pragma unroll
    for (int mt = 0; mt < 4; ++mt) {
        nxr[mt * 2 + 0] = -xnL[wm * 64 + mt * 16 + (l >> 2)];
        nxr[mt * 2 + 1] = -xnL[wm * 64 + mt * 16 + (l >> 2) + 8];
    }

    // ---- k_xx chunk first (B = x tile; overlaps the chunk-0/1 prefetch) ----
    {
        float cn[8];
#pragma unroll
        for (int nt = 0; nt < 4; ++nt) {
            cn[nt * 2 + 0] = xnL[wn * 32 + nt * 8 + (l & 3) * 2];
            cn[nt * 2 + 1] = xnL[wn * 32 + nt * 8 + (l & 3) * 2 + 1];
        }
        float s = wred(chunk_sum(Ahi, Ahi, aRow, bRow, klowA, klowB, mask, nxr, cn));
        if (l == 0) atomicAdd(&red[64], s);
    }

    // ---- 8 pairs of atom chunks ----
#pragma unroll 1
    for (int p = 0; p < 8; ++p) {
        __syncthreads();                         // prior pair's reads complete
        if (p < 7) {                             // prefetch chunks 2p+2, 2p+3
            const uint4* g = (const uint4*)g_at_h + (size_t)(2 * p + 2) * 1024;
            uint32_t d = sb + OFF_AT((2 * p + 2) & 3);   // contiguous 32KB pair
#pragma unroll
            for (int t = 0; t < 8; ++t) {
                int i = t * 256 + tid;
                cp16(d + i * 16, g + i);
            }
        }
        CP_COMMIT();
        CP_WAIT1();                              // chunks 2p, 2p+1 landed
        __syncthreads();

#pragma unroll
        for (int h = 0; h < 2; ++h) {
            const int ch = 2 * p + h;
            float cn[8];
#pragma unroll
            for (int nt = 0; nt < 4; ++nt) {
                cn[nt * 2 + 0] = __ldg(&g_anL[ch * 128 + wn * 32 + nt * 8 + (l & 3) * 2]);
                cn[nt * 2 + 1] = __ldg(&g_anL[ch * 128 + wn * 32 + nt * 8 + (l & 3) * 2 + 1]);
            }
            float s = wred(chunk_sum(Ahi, sb + OFF_AT(ch & 3),
                                     aRow, bRow, klowA, klowB, mask, nxr, cn));
            if (l == 0) atomicAdd(&red[ch * 4 + wn], s);
        }
    }

    __syncthreads();
    if (tid < NC) {
        float kyy = (g_kyy4[tid]           + g_kyy4[NC + tid] +
                     g_kyy4[2 * NC + tid]  + g_kyy4[3 * NC + tid])
                    * (1.0f / (NK * NK));
        float kxy = red[tid] * (1.0f / (NNOD * NK));
        float kxx = red[64]  * (1.0f / (NNOD * NNOD));
        out[b * NC + tid] = kxx + kyy - 2.0f * kxy;
    }
}

// ---------------------------------------------------------------------------
extern "C" void kernel_launch(void* const* d_in, const int* in_sizes, int n_in,
                              void* d_out, int out_size)
{
    const float* x     = (const float*)d_in[0];
    const float* atoms = (const float*)d_in[1];
    if (n_in >= 2 && in_sizes[0] == CKTOT * NDIM && in_sizes[1] == NBS * NNOD * NDIM) {
        x     = (const float*)d_in[1];
        atoms = (const float*)d_in[0];
    }
    float* out = (float*)d_out;

    cudaFuncSetAttribute(mmd_main, cudaFuncAttributeMaxDynamicSharedMemorySize, SMEM_DYN);

    mmd_prep<<<NC + 4 * NC, 128>>>(atoms);
    mmd_main<<<NBS, 256, SMEM_DYN>>>(x, out);
}

// round 14
// speedup vs baseline: 1.0584x; 1.0579x over previous
#include <cuda_runtime.h>
#include <cuda_fp16.h>
#include <cstdint>

#define NBS   256
#define NNOD  128
#define NDIM  64
#define NC    64
#define NK    32
#define CKTOT (NC*NK)

#define A2f 0.0225421101f     // log2(e)/64
#define C2f 0.0450842203f     // 2*log2(e)/64
#define S1f 0.21233045f       // sqrt(C2f): scale inputs so MMA acc = C2*dot

// ---------------- smem layout (byte offsets from 1KB-aligned base) ----------
#define OFF_XHI   0                     // 128x64 fp16 SW128 (16KB)
#define OFF_AT(b) (16384 + (b)*16384)   // 4 atom chunk bufs (fp16, 16KB each)
#define OFF_XNL   81920                 // float[128]
#define OFF_RED   82432                 // float[65]
#define SMEM_DYN  (82944 + 1024)

// pre-converted atoms: scaled fp16, already in SW128 tile byte order
static __device__ uint16_t g_at_h[CKTOT * NDIM];
static __device__ float    g_anL[CKTOT];   // A2*||atom_ck||^2
static __device__ float    g_kyy[NC];

// ---------------------------------------------------------------------------
__device__ __forceinline__ uint32_t smem_u32(const void* p) {
    uint32_t a;
    asm("{ .reg .u64 t; cvta.to.shared.u64 t, %1; cvt.u32.u64 %0, t; }" : "=r"(a) : "l"(p));
    return a;
}
__device__ __forceinline__ uint32_t sw128(uint32_t o) { return o ^ ((o >> 3) & 0x70); }

__device__ __forceinline__ void ldsm4(uint32_t r[4], uint32_t addr) {
    asm volatile("ldmatrix.sync.aligned.m8n8.x4.shared.b16 {%0,%1,%2,%3}, [%4];"
                 : "=r"(r[0]), "=r"(r[1]), "=r"(r[2]), "=r"(r[3]) : "r"(addr));
}
__device__ __forceinline__ void mma16816(float c[4], const uint32_t a[4], const uint32_t b[2]) {
    asm volatile("mma.sync.aligned.m16n8k16.row.col.f32.f16.f16.f32 "
                 "{%0,%1,%2,%3}, {%4,%5,%6,%7}, {%8,%9}, {%0,%1,%2,%3};"
                 : "+f"(c[0]), "+f"(c[1]), "+f"(c[2]), "+f"(c[3])
                 : "r"(a[0]), "r"(a[1]), "r"(a[2]), "r"(a[3]), "r"(b[0]), "r"(b[1]));
}
__device__ __forceinline__ void cp16(uint32_t dst, const void* src) {
    asm volatile("cp.async.cg.shared.global [%0], [%1], 16;" :: "r"(dst), "l"(src) : "memory");
}
#define CP_COMMIT() asm volatile("cp.async.commit_group;" ::: "memory")
#define CP_WAIT1()  asm volatile("cp.async.wait_group 1;" ::: "memory")

// MUFU exp2 (fp32 only — all fp16 exp paths and FMA offloads regressed/failed)
__device__ __forceinline__ float mexp2(float x) {
    float r;
    asm("ex2.approx.f32 %0, %1;" : "=f"(r) : "f"(x));
    return r;
}
// FMA-pipe exp2 for the (tiny) prep kernel
__device__ __forceinline__ float fexp2(float x) {
    float r = x + 12582912.0f;
    int   m = __float_as_int(r);
    float t = x - (r - 12582912.0f);
    float p =            1.3333558e-3f;
    p = fmaf(p, t, 9.6181291e-3f);
    p = fmaf(p, t, 5.5504109e-2f);
    p = fmaf(p, t, 2.4022651e-1f);
    p = fmaf(p, t, 6.9314718e-1f);
    p = fmaf(p, t, 1.0f);
    return __int_as_float(__float_as_int(p) + (m << 23));
}
__device__ __forceinline__ float wred(float v) {
#pragma unroll
    for (int o = 16; o; o >>= 1) v += __shfl_xor_sync(0xffffffffu, v, o);
    return v;
}

// ---------------------------------------------------------------------------
// Prep (R7 form): per-ck-row scaled norms, k_yy, fp16 atoms pre-swizzled
// ---------------------------------------------------------------------------
__global__ void mmd_prep(const float* __restrict__ atoms)
{
    __shared__ float at[NK][NDIM + 4];
    __shared__ float anl[NK];
    __shared__ float ssum;
    const int c = blockIdx.x, tid = threadIdx.x;

    const float4* ag = (const float4*)(atoms + (size_t)c * NK * NDIM);
#pragma unroll
    for (int t = 0; t < 4; ++t) {
        int idx = t * 128 + tid;
        int row = idx >> 4, k4 = idx & 15;
        *(float4*)&at[row][k4 * 4] = ag[idx];
    }
    if (tid == 0) ssum = 0.0f;
    __syncthreads();

    if (tid < NK) {
        float s = 0.0f;
#pragma unroll
        for (int k = 0; k < NDIM; k += 4) {
            float4 v = *(const float4*)&at[tid][k];
            s = fmaf(v.x, v.x, fmaf(v.y, v.y, fmaf(v.z, v.z, fmaf(v.w, v.w, s))));
        }
        anl[tid] = s;
        g_anL[c * NK + tid] = s * A2f;
    }
    __syncthreads();

#pragma unroll
    for (int t = 0; t < 16; ++t) {
        int idx = t * 128 + tid;            // 0..2047
        int r = idx >> 6, k = idx & 63;
        float v = at[r][k] * S1f;
        int gr = c * NK + r;
        int chunk = gr >> 7, rin = gr & 127;
        uint32_t off = sw128((uint32_t)(rin * 128 + k * 2));
        g_at_h[(uint32_t)chunk * 8192u + (off >> 1)] =
            __half_as_ushort(__float2half_rn(v));
    }

    float ps = 0.0f;
#pragma unroll
    for (int t = 0; t < 8; ++t) {
        int p = t * 128 + tid;
        int i = p >> 5, j = p & 31;
        float dot = 0.0f;
#pragma unroll
        for (int k = 0; k < NDIM; k += 4) {
            float4 a  = *(const float4*)&at[i][k];
            float4 bb = *(const float4*)&at[j][k];
            dot = fmaf(a.x, bb.x, fmaf(a.y, bb.y, fmaf(a.z, bb.z, fmaf(a.w, bb.w, dot))));
        }
        ps += fexp2(fmaf(dot, C2f, -A2f * (anl[i] + anl[j])));
    }
    ps = wred(ps);
    if ((tid & 31) == 0) atomicAdd(&ssum, ps);
    __syncthreads();
    if (tid == 0) g_kyy[c] = ssum * (1.0f / (NK * NK));
}

// ---------------------------------------------------------------------------
// One 128x128 chunk, warp tile 32x64, A fragments PERSISTENT in registers
// (loaded once per kernel — per-chunk LDSM is B-only: 16 instead of 24).
// Two per-atom partial sums out (warp spans 2 atoms).
// ---------------------------------------------------------------------------
__device__ __forceinline__ void chunk_sum2(
    const uint32_t af[8][4], uint32_t Bb,
    uint32_t bRow, uint32_t klowB, uint32_t mask,
    const float nxr[4], const float cn[16], float& outA, float& outB)
{
    float c[2][8][4];
#pragma unroll
    for (int nt = 0; nt < 8; ++nt)
#pragma unroll
        for (int mt = 0; mt < 2; ++mt) {
            c[mt][nt][0] = nxr[mt * 2 + 0] - cn[nt * 2 + 0];
            c[mt][nt][1] = nxr[mt * 2 + 0] - cn[nt * 2 + 1];
            c[mt][nt][2] = nxr[mt * 2 + 1] - cn[nt * 2 + 0];
            c[mt][nt][3] = nxr[mt * 2 + 1] - cn[nt * 2 + 1];
        }

#pragma unroll
    for (int ks = 0; ks < 4; ++ks) {
        const uint32_t colB = ((uint32_t)(ks * 32) + klowB) ^ mask;
        {   // cols wn*64 .. +31 (atom A half)
            uint32_t b0[4], b1[4];
            ldsm4(b0, Bb + bRow + colB);
            ldsm4(b1, Bb + bRow + 2048 + colB);
#pragma unroll
            for (int mt = 0; mt < 2; ++mt) {
                mma16816(c[mt][0], af[mt * 4 + ks], b0 + 0);
                mma16816(c[mt][1], af[mt * 4 + ks], b0 + 2);
                mma16816(c[mt][2], af[mt * 4 + ks], b1 + 0);
                mma16816(c[mt][3], af[mt * 4 + ks], b1 + 2);
            }
        }
        {   // cols wn*64+32 .. +63 (atom B half)
            uint32_t b2[4], b3[4];
            ldsm4(b2, Bb + bRow + 4096 + colB);
            ldsm4(b3, Bb + bRow + 6144 + colB);
#pragma unroll
            for (int mt = 0; mt < 2; ++mt) {
                mma16816(c[mt][4], af[mt * 4 + ks], b2 + 0);
                mma16816(c[mt][5], af[mt * 4 + ks], b2 + 2);
                mma16816(c[mt][6], af[mt * 4 + ks], b3 + 0);
                mma16816(c[mt][7], af[mt * 4 + ks], b3 + 2);
            }
        }
    }

    float a0 = 0.f, a1 = 0.f, b0s = 0.f, b1s = 0.f;
#pragma unroll
    for (int mt = 0; mt < 2; ++mt) {
#pragma unroll
        for (int nt = 0; nt < 4; ++nt) {
            a0 += mexp2(c[mt][nt][0]);
            a1 += mexp2(c[mt][nt][1]);
            a0 += mexp2(c[mt][nt][2]);
            a1 += mexp2(c[mt][nt][3]);
        }
#pragma unroll
        for (int nt = 4; nt < 8; ++nt) {
            b0s += mexp2(c[mt][nt][0]);
            b1s += mexp2(c[mt][nt][1]);
            b0s += mexp2(c[mt][nt][2]);
            b1s += mexp2(c[mt][nt][3]);
        }
    }
    outA = a0 + a1;
    outB = b0s + b1s;
}

// ---------------------------------------------------------------------------
// Main: one CTA per graph; kxx first (overlaps prefetch), then 8 chunk-pairs.
// ---------------------------------------------------------------------------
__global__ void __launch_bounds__(256, 2)
mmd_main(const float* __restrict__ x, float* __restrict__ out)
{
    extern __shared__ char sraw[];
    char* sm = (char*)(((uintptr_t)sraw + 1023) & ~(uintptr_t)1023);
    const uint32_t sb = smem_u32(sm);

    float* xnL = (float*)(sm + OFF_XNL);
    float* red = (float*)(sm + OFF_RED);

    const int tid = threadIdx.x, wid = tid >> 5, l = tid & 31;
    const int b  = blockIdx.x;
    const int wm = wid >> 1;      // row quarter -> rows wm*32..+31
    const int wn = wid & 1;       // col half    -> cols wn*64..+63 = 2 atoms

    if (tid < 65) red[tid] = 0.0f;

    // ---- prefetch chunks 0,1 into bufs 0,1 (one contiguous 32KB group) ----
    {
        const uint4* g = (const uint4*)g_at_h;
        uint32_t d = sb + OFF_AT(0);
#pragma unroll
        for (int t = 0; t < 8; ++t) {
            int i = t * 256 + tid;
            cp16(d + i * 16, g + i);
        }
        CP_COMMIT();
    }

    // ---- x tile: scaled fp16 into SW128 smem ----
    const float4* xg = (const float4*)(x + (size_t)b * NNOD * NDIM);
#pragma unroll
    for (int t = 0; t < 8; ++t) {
        int idx = t * 256 + tid;               // 0..2047 float4
        int row = idx >> 4, k4 = idx & 15;
        float4 v = xg[idx];
        __half h0 = __float2half_rn(v.x * S1f), h1 = __float2half_rn(v.y * S1f);
        __half h2 = __float2half_rn(v.z * S1f), h3 = __float2half_rn(v.w * S1f);
        uint32_t off = sw128((uint32_t)(row * 128 + k4 * 8));
        uint2 ph;
        ph.x = (uint32_t)__half_as_ushort(h0) | ((uint32_t)__half_as_ushort(h1) << 16);
        ph.y = (uint32_t)__half_as_ushort(h2) | ((uint32_t)__half_as_ushort(h3) << 16);
        *(uint2*)(sm + OFF_XHI + off) = ph;
    }
    if (tid < NNOD) {
        const float4* xr4 = (const float4*)(x + ((size_t)b * NNOD + tid) * NDIM);
        float s = 0.0f;
#pragma unroll
        for (int k = 0; k < 16; ++k) {
            float4 v = xr4[k];
            s = fmaf(v.x, v.x, fmaf(v.y, v.y, fmaf(v.z, v.z, fmaf(v.w, v.w, s))));
        }
        xnL[tid] = s * A2f;
    }
    __syncthreads();

    // ---- per-thread ldmatrix address components ----
    const uint32_t mask  = (uint32_t)((l & 7) << 4);
    const uint32_t aRow  = (uint32_t)((wm * 32 + (l & 7) + ((l >> 3) & 1) * 8) * 128);
    const uint32_t klowA = (uint32_t)(((l >> 4) & 1) * 16);
    const uint32_t bRow  = (uint32_t)((wn * 64 + (l & 7) + ((l >> 4) & 1) * 8) * 128);
    const uint32_t klowB = (uint32_t)(((l >> 3) & 1) * 16);
    const uint32_t Ahi   = sb + OFF_XHI;

    // ---- A fragments: loaded ONCE, reused by all 17 chunks ----
    uint32_t af[8][4];
#pragma unroll
    for (int mt = 0; mt < 2; ++mt)
#pragma unroll
        for (int ks = 0; ks < 4; ++ks)
            ldsm4(af[mt * 4 + ks],
                  Ahi + aRow + mt * 2048 + (((uint32_t)(ks * 32) + klowA) ^ mask));

    // negated row norms: rows wm*32 + mt*16 + (l>>2) + r*8
    float nxr[4];
#pragma unroll
    for (int mt = 0; mt < 2; ++mt) {
        nxr[mt * 2 + 0] = -xnL[wm * 32 + mt * 16 + (l >> 2)];
        nxr[mt * 2 + 1] = -xnL[wm * 32 + mt * 16 + (l >> 2) + 8];
    }

    // ---- k_xx chunk first (B = x tile; overlaps the chunk-0/1 prefetch) ----
    {
        float cn[16];
#pragma unroll
        for (int nt = 0; nt < 8; ++nt) {
            cn[nt * 2 + 0] = xnL[wn * 64 + nt * 8 + (l & 3) * 2];
            cn[nt * 2 + 1] = xnL[wn * 64 + nt * 8 + (l & 3) * 2 + 1];
        }
        float sA, sB;
        chunk_sum2(af, Ahi, bRow, klowB, mask, nxr, cn, sA, sB);
        float s = wred(sA + sB);
        if (l == 0) atomicAdd(&red[64], s);
    }

    // ---- 8 pairs of atom chunks ----
#pragma unroll 1
    for (int p = 0; p < 8; ++p) {
        __syncthreads();                         // prior pair's reads complete
        if (p < 7) {                             // prefetch chunks 2p+2, 2p+3
            const uint4* g = (const uint4*)g_at_h + (size_t)(2 * p + 2) * 1024;
            uint32_t d = sb + OFF_AT((2 * p + 2) & 3);   // contiguous 32KB pair
#pragma unroll
            for (int t = 0; t < 8; ++t) {
                int i = t * 256 + tid;
                cp16(d + i * 16, g + i);
            }
        }
        CP_COMMIT();
        CP_WAIT1();                              // chunks 2p, 2p+1 landed
        __syncthreads();

#pragma unroll
        for (int h = 0; h < 2; ++h) {
            const int ch = 2 * p + h;
            float cn[16];
#pragma unroll
            for (int nt = 0; nt < 8; ++nt) {
                cn[nt * 2 + 0] = __ldg(&g_anL[ch * 128 + wn * 64 + nt * 8 + (l & 3) * 2]);
                cn[nt * 2 + 1] = __ldg(&g_anL[ch * 128 + wn * 64 + nt * 8 + (l & 3) * 2 + 1]);
            }
            float sA, sB;
            chunk_sum2(af, sb + OFF_AT(ch & 3), bRow, klowB, mask, nxr, cn, sA, sB);
            sA = wred(sA);
            sB = wred(sB);
            if (l == 0) {
                atomicAdd(&red[ch * 4 + wn * 2 + 0], sA);
                atomicAdd(&red[ch * 4 + wn * 2 + 1], sB);
            }
        }
    }

    __syncthreads();
    if (tid < NC) {
        float kxy = red[tid] * (1.0f / (NNOD * NK));
        float kxx = red[64]  * (1.0f / (NNOD * NNOD));
        out[b * NC + tid] = kxx + g_kyy[tid] - 2.0f * kxy;
    }
}

// ---------------------------------------------------------------------------
extern "C" void kernel_launch(void* const* d_in, const int* in_sizes, int n_in,
                              void* d_out, int out_size)
{
    const float* x     = (const float*)d_in[0];
    const float* atoms = (const float*)d_in[1];
    if (n_in >= 2 && in_sizes[0] == CKTOT * NDIM && in_sizes[1] == NBS * NNOD * NDIM) {
        x     = (const float*)d_in[1];
        atoms = (const float*)d_in[0];
    }
    float* out = (float*)d_out;

    cudaFuncSetAttribute(mmd_main, cudaFuncAttributeMaxDynamicSharedMemorySize, SMEM_DYN);

    mmd_prep<<<NC, 128>>>(atoms);
    mmd_main<<<NBS, 256, SMEM_DYN>>>(x, out);
}

// round 15
// speedup vs baseline: 1.0775x; 1.0180x over previous
#include <cuda_runtime.h>
#include <cuda_fp16.h>
#include <cstdint>

#define NBS   256
#define NNOD  128
#define NDIM  64
#define NC    64
#define NK    32
#define CKTOT (NC*NK)

#define A2f 0.0225421101f     // log2(e)/64
#define C2f 0.0450842203f     // 2*log2(e)/64
#define S1f 0.21233045f       // sqrt(C2f): scale inputs so MMA acc = C2*dot

// ---------------- smem layout (byte offsets from 1KB-aligned base) ----------
#define OFF_XHI   0                     // 128x64 fp16 SW128 (16KB)
#define OFF_AT(b) (16384 + (b)*16384)   // 4 atom chunk bufs (fp16, 16KB each)
#define OFF_XNL   81920                 // float[128]
#define OFF_RED   82432                 // float[65]
#define SMEM_DYN  (82944 + 1024)

// pre-converted atoms: scaled fp16, already in SW128 tile byte order
static __device__ uint16_t g_at_h[CKTOT * NDIM];
static __device__ float    g_anL[CKTOT];   // A2*||atom_ck||^2
static __device__ float    g_kyy[NC];

// ---------------------------------------------------------------------------
__device__ __forceinline__ uint32_t smem_u32(const void* p) {
    uint32_t a;
    asm("{ .reg .u64 t; cvta.to.shared.u64 t, %1; cvt.u32.u64 %0, t; }" : "=r"(a) : "l"(p));
    return a;
}
__device__ __forceinline__ uint32_t sw128(uint32_t o) { return o ^ ((o >> 3) & 0x70); }

__device__ __forceinline__ void ldsm4(uint32_t r[4], uint32_t addr) {
    asm volatile("ldmatrix.sync.aligned.m8n8.x4.shared.b16 {%0,%1,%2,%3}, [%4];"
                 : "=r"(r[0]), "=r"(r[1]), "=r"(r[2]), "=r"(r[3]) : "r"(addr));
}
__device__ __forceinline__ void mma16816(float c[4], const uint32_t a[4], const uint32_t b[2]) {
    asm volatile("mma.sync.aligned.m16n8k16.row.col.f32.f16.f16.f32 "
                 "{%0,%1,%2,%3}, {%4,%5,%6,%7}, {%8,%9}, {%0,%1,%2,%3};"
                 : "+f"(c[0]), "+f"(c[1]), "+f"(c[2]), "+f"(c[3])
                 : "r"(a[0]), "r"(a[1]), "r"(a[2]), "r"(a[3]), "r"(b[0]), "r"(b[1]));
}
__device__ __forceinline__ void cp16(uint32_t dst, const void* src) {
    asm volatile("cp.async.cg.shared.global [%0], [%1], 16;" :: "r"(dst), "l"(src) : "memory");
}
#define CP_COMMIT() asm volatile("cp.async.commit_group;" ::: "memory")
#define CP_WAIT1()  asm volatile("cp.async.wait_group 1;" ::: "memory")

// PDL controls (sm_90+; plain sm_100-legal)
#define GDC_LAUNCH_DEPENDENTS() asm volatile("griddepcontrol.launch_dependents;" ::: "memory")
#define GDC_WAIT()              asm volatile("griddepcontrol.wait;" ::: "memory")

// MUFU exp2 (fp32 only — all fp16 exp paths and FMA offloads regressed/failed)
__device__ __forceinline__ float mexp2(float x) {
    float r;
    asm("ex2.approx.f32 %0, %1;" : "=f"(r) : "f"(x));
    return r;
}
// FMA-pipe exp2 for the (tiny) prep kernel
__device__ __forceinline__ float fexp2(float x) {
    float r = x + 12582912.0f;
    int   m = __float_as_int(r);
    float t = x - (r - 12582912.0f);
    float p =            1.3333558e-3f;
    p = fmaf(p, t, 9.6181291e-3f);
    p = fmaf(p, t, 5.5504109e-2f);
    p = fmaf(p, t, 2.4022651e-1f);
    p = fmaf(p, t, 6.9314718e-1f);
    p = fmaf(p, t, 1.0f);
    return __int_as_float(__float_as_int(p) + (m << 23));
}
__device__ __forceinline__ float wred(float v) {
#pragma unroll
    for (int o = 16; o; o >>= 1) v += __shfl_xor_sync(0xffffffffu, v, o);
    return v;
}

// ---------------------------------------------------------------------------
// Prep (R7 form): per-ck-row scaled norms, k_yy, fp16 atoms pre-swizzled.
// Signals PDL dependents immediately so mmd_main's prefix overlaps.
// ---------------------------------------------------------------------------
__global__ void mmd_prep(const float* __restrict__ atoms)
{
    GDC_LAUNCH_DEPENDENTS();

    __shared__ float at[NK][NDIM + 4];
    __shared__ float anl[NK];
    __shared__ float ssum;
    const int c = blockIdx.x, tid = threadIdx.x;

    const float4* ag = (const float4*)(atoms + (size_t)c * NK * NDIM);
#pragma unroll
    for (int t = 0; t < 4; ++t) {
        int idx = t * 128 + tid;
        int row = idx >> 4, k4 = idx & 15;
        *(float4*)&at[row][k4 * 4] = ag[idx];
    }
    if (tid == 0) ssum = 0.0f;
    __syncthreads();

    if (tid < NK) {
        float s = 0.0f;
#pragma unroll
        for (int k = 0; k < NDIM; k += 4) {
            float4 v = *(const float4*)&at[tid][k];
            s = fmaf(v.x, v.x, fmaf(v.y, v.y, fmaf(v.z, v.z, fmaf(v.w, v.w, s))));
        }
        anl[tid] = s;
        g_anL[c * NK + tid] = s * A2f;
    }
    __syncthreads();

#pragma unroll
    for (int t = 0; t < 16; ++t) {
        int idx = t * 128 + tid;            // 0..2047
        int r = idx >> 6, k = idx & 63;
        float v = at[r][k] * S1f;
        int gr = c * NK + r;
        int chunk = gr >> 7, rin = gr & 127;
        uint32_t off = sw128((uint32_t)(rin * 128 + k * 2));
        g_at_h[(uint32_t)chunk * 8192u + (off >> 1)] =
            __half_as_ushort(__float2half_rn(v));
    }

    float ps = 0.0f;
#pragma unroll
    for (int t = 0; t < 8; ++t) {
        int p = t * 128 + tid;
        int i = p >> 5, j = p & 31;
        float dot = 0.0f;
#pragma unroll
        for (int k = 0; k < NDIM; k += 4) {
            float4 a  = *(const float4*)&at[i][k];
            float4 bb = *(const float4*)&at[j][k];
            dot = fmaf(a.x, bb.x, fmaf(a.y, bb.y, fmaf(a.z, bb.z, fmaf(a.w, bb.w, dot))));
        }
        ps += fexp2(fmaf(dot, C2f, -A2f * (anl[i] + anl[j])));
    }
    ps = wred(ps);
    if ((tid & 31) == 0) atomicAdd(&ssum, ps);
    __syncthreads();
    if (tid == 0) g_kyy[c] = ssum * (1.0f / (NK * NK));
}

// ---------------------------------------------------------------------------
// One 128x128 chunk, warp tile 64x32 (ks-outer, R7 form):
// MMA (norms folded into acc init) + fp32 MUFU ex2 epilogue.
// ---------------------------------------------------------------------------
__device__ __forceinline__ float chunk_sum(
    uint32_t Ahi, uint32_t Bb,
    uint32_t aRow, uint32_t bRow, uint32_t klowA, uint32_t klowB, uint32_t mask,
    const float nxr[8], const float cn[8])
{
    float c[4][4][4];
#pragma unroll
    for (int mt = 0; mt < 4; ++mt)
#pragma unroll
        for (int nt = 0; nt < 4; ++nt) {
            c[mt][nt][0] = nxr[mt * 2 + 0] - cn[nt * 2 + 0];
            c[mt][nt][1] = nxr[mt * 2 + 0] - cn[nt * 2 + 1];
            c[mt][nt][2] = nxr[mt * 2 + 1] - cn[nt * 2 + 0];
            c[mt][nt][3] = nxr[mt * 2 + 1] - cn[nt * 2 + 1];
        }

#pragma unroll
    for (int ks = 0; ks < 4; ++ks) {
        const uint32_t colA = ((uint32_t)(ks * 32) + klowA) ^ mask;
        const uint32_t colB = ((uint32_t)(ks * 32) + klowB) ^ mask;
        uint32_t b0[4], b1[4];
        ldsm4(b0, Bb + bRow + colB);            // cols wn*32 .. +15
        ldsm4(b1, Bb + bRow + 2048 + colB);     // cols +16 .. +31
#pragma unroll
        for (int mt = 0; mt < 4; ++mt) {
            uint32_t a[4];
            ldsm4(a, Ahi + aRow + mt * 2048 + colA);
            mma16816(c[mt][0], a, b0 + 0);
            mma16816(c[mt][1], a, b0 + 2);
            mma16816(c[mt][2], a, b1 + 0);
            mma16816(c[mt][3], a, b1 + 2);
        }
    }

    float s0 = 0.f, s1 = 0.f, s2 = 0.f, s3 = 0.f;
#pragma unroll
    for (int mt = 0; mt < 4; ++mt)
#pragma unroll
        for (int nt = 0; nt < 4; ++nt) {
            s0 += mexp2(c[mt][nt][0]);
            s1 += mexp2(c[mt][nt][1]);
            s2 += mexp2(c[mt][nt][2]);
            s3 += mexp2(c[mt][nt][3]);
        }
    return (s0 + s1) + (s2 + s3);
}

// ---------------------------------------------------------------------------
// Main: one CTA per graph. PDL prefix: x-convert + norms run BEFORE the
// griddepcontrol.wait; atom prefetch + kxx after (kxx covers prefetch).
// ---------------------------------------------------------------------------
__global__ void __launch_bounds__(256, 2)
mmd_main(const float* __restrict__ x, float* __restrict__ out)
{
    extern __shared__ char sraw[];
    char* sm = (char*)(((uintptr_t)sraw + 1023) & ~(uintptr_t)1023);
    const uint32_t sb = smem_u32(sm);

    float* xnL = (float*)(sm + OFF_XNL);
    float* red = (float*)(sm + OFF_RED);

    const int tid = threadIdx.x, wid = tid >> 5, l = tid & 31;
    const int b  = blockIdx.x;
    const int wm = wid >> 2;      // row half    -> rows wm*64..+63
    const int wn = wid & 3;       // col quarter -> cols wn*32..+31 = one atom

    if (tid < 65) red[tid] = 0.0f;

    // ---- prep-independent prefix: x tile conversion + norms ----
    const float4* xg = (const float4*)(x + (size_t)b * NNOD * NDIM);
#pragma unroll
    for (int t = 0; t < 8; ++t) {
        int idx = t * 256 + tid;               // 0..2047 float4
        int row = idx >> 4, k4 = idx & 15;
        float4 v = xg[idx];
        __half h0 = __float2half_rn(v.x * S1f), h1 = __float2half_rn(v.y * S1f);
        __half h2 = __float2half_rn(v.z * S1f), h3 = __float2half_rn(v.w * S1f);
        uint32_t off = sw128((uint32_t)(row * 128 + k4 * 8));
        uint2 ph;
        ph.x = (uint32_t)__half_as_ushort(h0) | ((uint32_t)__half_as_ushort(h1) << 16);
        ph.y = (uint32_t)__half_as_ushort(h2) | ((uint32_t)__half_as_ushort(h3) << 16);
        *(uint2*)(sm + OFF_XHI + off) = ph;
    }
    if (tid < NNOD) {
        const float4* xr4 = (const float4*)(x + ((size_t)b * NNOD + tid) * NDIM);
        float s = 0.0f;
#pragma unroll
        for (int k = 0; k < 16; ++k) {
            float4 v = xr4[k];
            s = fmaf(v.x, v.x, fmaf(v.y, v.y, fmaf(v.z, v.z, fmaf(v.w, v.w, s))));
        }
        xnL[tid] = s * A2f;
    }
    __syncthreads();

    // ---- wait for prep's results to be visible, then start atom traffic ----
    GDC_WAIT();
    {
        const uint4* g = (const uint4*)g_at_h;
        uint32_t d = sb + OFF_AT(0);
#pragma unroll
        for (int t = 0; t < 8; ++t) {
            int i = t * 256 + tid;
            cp16(d + i * 16, g + i);
        }
        CP_COMMIT();
    }

    // ---- per-thread ldmatrix address components ----
    const uint32_t mask  = (uint32_t)((l & 7) << 4);
    const uint32_t aRow  = (uint32_t)((wm * 64 + (l & 7) + ((l >> 3) & 1) * 8) * 128);
    const uint32_t klowA = (uint32_t)(((l >> 4) & 1) * 16);
    const uint32_t bRow  = (uint32_t)((wn * 32 + (l & 7) + ((l >> 4) & 1) * 8) * 128);
    const uint32_t klowB = (uint32_t)(((l >> 3) & 1) * 16);
    const uint32_t Ahi   = sb + OFF_XHI;

    // negated row norms: rows wm*64 + mt*16 + (l>>2) + r*8
    float nxr[8];
#pragma unroll
    for (int mt = 0; mt < 4; ++mt) {
        nxr[mt * 2 + 0] = -xnL[wm * 64 + mt * 16 + (l >> 2)];
        nxr[mt * 2 + 1] = -xnL[wm * 64 + mt * 16 + (l >> 2) + 8];
    }

    // ---- k_xx chunk (B = x tile; covers the chunk-0/1 prefetch latency) ----
    {
        float cn[8];
#pragma unroll
        for (int nt = 0; nt < 4; ++nt) {
            cn[nt * 2 + 0] = xnL[wn * 32 + nt * 8 + (l & 3) * 2];
            cn[nt * 2 + 1] = xnL[wn * 32 + nt * 8 + (l & 3) * 2 + 1];
        }
        float s = wred(chunk_sum(Ahi, Ahi, aRow, bRow, klowA, klowB, mask, nxr, cn));
        if (l == 0) atomicAdd(&red[64], s);
    }

    // ---- 8 pairs of atom chunks ----
#pragma unroll 1
    for (int p = 0; p < 8; ++p) {
        __syncthreads();                         // prior pair's reads complete
        if (p < 7) {                             // prefetch chunks 2p+2, 2p+3
            const uint4* g = (const uint4*)g_at_h + (size_t)(2 * p + 2) * 1024;
            uint32_t d = sb + OFF_AT((2 * p + 2) & 3);   // contiguous 32KB pair
#pragma unroll
            for (int t = 0; t < 8; ++t) {
                int i = t * 256 + tid;
                cp16(d + i * 16, g + i);
            }
        }
        CP_COMMIT();
        CP_WAIT1();                              // chunks 2p, 2p+1 landed
        __syncthreads();

#pragma unroll
        for (int h = 0; h < 2; ++h) {
            const int ch = 2 * p + h;
            float cn[8];
#pragma unroll
            for (int nt = 0; nt < 4; ++nt) {
                cn[nt * 2 + 0] = __ldg(&g_anL[ch * 128 + wn * 32 + nt * 8 + (l & 3) * 2]);
                cn[nt * 2 + 1] = __ldg(&g_anL[ch * 128 + wn * 32 + nt * 8 + (l & 3) * 2 + 1]);
            }
            float s = wred(chunk_sum(Ahi, sb + OFF_AT(ch & 3),
                                     aRow, bRow, klowA, klowB, mask, nxr, cn));
            if (l == 0) atomicAdd(&red[ch * 4 + wn], s);
        }
    }

    __syncthreads();
    if (tid < NC) {
        float kxy = red[tid] * (1.0f / (NNOD * NK));
        float kxx = red[64]  * (1.0f / (NNOD * NNOD));
        out[b * NC + tid] = kxx + g_kyy[tid] - 2.0f * kxy;
    }
}

// ---------------------------------------------------------------------------
extern "C" void kernel_launch(void* const* d_in, const int* in_sizes, int n_in,
                              void* d_out, int out_size)
{
    const float* x     = (const float*)d_in[0];
    const float* atoms = (const float*)d_in[1];
    if (n_in >= 2 && in_sizes[0] == CKTOT * NDIM && in_sizes[1] == NBS * NNOD * NDIM) {
        x     = (const float*)d_in[1];
        atoms = (const float*)d_in[0];
    }
    float* out = (float*)d_out;

    cudaFuncSetAttribute(mmd_main, cudaFuncAttributeMaxDynamicSharedMemorySize, SMEM_DYN);

    mmd_prep<<<NC, 128>>>(atoms);

    // main launched with PDL so it starts while prep is still running
    cudaLaunchConfig_t cfg = {};
    cfg.gridDim        = dim3(NBS);
    cfg.blockDim       = dim3(256);
    cfg.dynamicSmemBytes = SMEM_DYN;
    cfg.stream         = 0;
    cudaLaunchAttribute attr[1];
    attr[0].id = cudaLaunchAttributeProgrammaticStreamSerialization;
    attr[0].val.programmaticStreamSerializationAllowed = 1;
    cfg.attrs    = attr;
    cfg.numAttrs = 1;
    cudaLaunchKernelEx(&cfg, mmd_main, x, out);
}

// round 16
// speedup vs baseline: 1.0966x; 1.0177x over previous
#include <cuda_runtime.h>
#include <cuda_fp16.h>
#include <cstdint>

#define NBS   256
#define NNOD  128
#define NDIM  64
#define NC    64
#define NK    32
#define CKTOT (NC*NK)

#define A2f 0.0225421101f     // log2(e)/64
#define C2f 0.0450842203f     // 2*log2(e)/64
#define S1f 0.21233045f       // sqrt(C2f): scale inputs so MMA acc = C2*dot

// ---------------- smem layout (byte offsets from 1KB-aligned base) ----------
#define OFF_XHI   0                     // 128x64 fp16 SW128 (16KB)
#define OFF_AT(b) (16384 + (b)*16384)   // 4 atom chunk bufs (fp16, 16KB each)
#define OFF_XNL   81920                 // float[128]
#define OFF_RED   82432                 // float[65]
#define SMEM_DYN  (82944 + 1024)

// pre-converted atoms: scaled fp16, already in SW128 tile byte order
static __device__ uint16_t g_at_h[CKTOT * NDIM];
static __device__ float    g_anL[CKTOT];   // A2*||atom_ck||^2
static __device__ float    g_kyy[NC];

// ---------------------------------------------------------------------------
__device__ __forceinline__ uint32_t smem_u32(const void* p) {
    uint32_t a;
    asm("{ .reg .u64 t; cvta.to.shared.u64 t, %1; cvt.u32.u64 %0, t; }" : "=r"(a) : "l"(p));
    return a;
}
__device__ __forceinline__ uint32_t sw128(uint32_t o) { return o ^ ((o >> 3) & 0x70); }

__device__ __forceinline__ void ldsm4(uint32_t r[4], uint32_t addr) {
    asm volatile("ldmatrix.sync.aligned.m8n8.x4.shared.b16 {%0,%1,%2,%3}, [%4];"
                 : "=r"(r[0]), "=r"(r[1]), "=r"(r[2]), "=r"(r[3]) : "r"(addr));
}
__device__ __forceinline__ void mma16816(float c[4], const uint32_t a[4], const uint32_t b[2]) {
    asm volatile("mma.sync.aligned.m16n8k16.row.col.f32.f16.f16.f32 "
                 "{%0,%1,%2,%3}, {%4,%5,%6,%7}, {%8,%9}, {%0,%1,%2,%3};"
                 : "+f"(c[0]), "+f"(c[1]), "+f"(c[2]), "+f"(c[3])
                 : "r"(a[0]), "r"(a[1]), "r"(a[2]), "r"(a[3]), "r"(b[0]), "r"(b[1]));
}
__device__ __forceinline__ void cp16(uint32_t dst, const void* src) {
    asm volatile("cp.async.cg.shared.global [%0], [%1], 16;" :: "r"(dst), "l"(src) : "memory");
}
#define CP_COMMIT() asm volatile("cp.async.commit_group;" ::: "memory")
#define CP_WAIT1()  asm volatile("cp.async.wait_group 1;" ::: "memory")

// PDL controls (sm_90+; plain sm_100-legal)
#define GDC_LAUNCH_DEPENDENTS() asm volatile("griddepcontrol.launch_dependents;" ::: "memory")
#define GDC_WAIT()              asm volatile("griddepcontrol.wait;" ::: "memory")

// MUFU exp2 (fp32 only — all fp16 exp paths and FMA offloads regressed/failed)
__device__ __forceinline__ float mexp2(float x) {
    float r;
    asm("ex2.approx.f32 %0, %1;" : "=f"(r) : "f"(x));
    return r;
}
// FMA-pipe exp2 for the (tiny) prep kernel
__device__ __forceinline__ float fexp2(float x) {
    float r = x + 12582912.0f;
    int   m = __float_as_int(r);
    float t = x - (r - 12582912.0f);
    float p =            1.3333558e-3f;
    p = fmaf(p, t, 9.6181291e-3f);
    p = fmaf(p, t, 5.5504109e-2f);
    p = fmaf(p, t, 2.4022651e-1f);
    p = fmaf(p, t, 6.9314718e-1f);
    p = fmaf(p, t, 1.0f);
    return __int_as_float(__float_as_int(p) + (m << 23));
}
__device__ __forceinline__ float wred(float v) {
#pragma unroll
    for (int o = 16; o; o >>= 1) v += __shfl_xor_sync(0xffffffffu, v, o);
    return v;
}

// ---------------------------------------------------------------------------
// Prep (R7 form): per-ck-row scaled norms, k_yy, fp16 atoms pre-swizzled.
// Signals PDL dependents immediately so mmd_main's prefix overlaps.
// ---------------------------------------------------------------------------
__global__ void mmd_prep(const float* __restrict__ atoms)
{
    GDC_LAUNCH_DEPENDENTS();

    __shared__ float at[NK][NDIM + 4];
    __shared__ float anl[NK];
    __shared__ float ssum;
    const int c = blockIdx.x, tid = threadIdx.x;

    const float4* ag = (const float4*)(atoms + (size_t)c * NK * NDIM);
#pragma unroll
    for (int t = 0; t < 4; ++t) {
        int idx = t * 128 + tid;
        int row = idx >> 4, k4 = idx & 15;
        *(float4*)&at[row][k4 * 4] = ag[idx];
    }
    if (tid == 0) ssum = 0.0f;
    __syncthreads();

    if (tid < NK) {
        float s = 0.0f;
#pragma unroll
        for (int k = 0; k < NDIM; k += 4) {
            float4 v = *(const float4*)&at[tid][k];
            s = fmaf(v.x, v.x, fmaf(v.y, v.y, fmaf(v.z, v.z, fmaf(v.w, v.w, s))));
        }
        anl[tid] = s;
        g_anL[c * NK + tid] = s * A2f;
    }
    __syncthreads();

#pragma unroll
    for (int t = 0; t < 16; ++t) {
        int idx = t * 128 + tid;            // 0..2047
        int r = idx >> 6, k = idx & 63;
        float v = at[r][k] * S1f;
        int gr = c * NK + r;
        int chunk = gr >> 7, rin = gr & 127;
        uint32_t off = sw128((uint32_t)(rin * 128 + k * 2));
        g_at_h[(uint32_t)chunk * 8192u + (off >> 1)] =
            __half_as_ushort(__float2half_rn(v));
    }

    float ps = 0.0f;
#pragma unroll
    for (int t = 0; t < 8; ++t) {
        int p = t * 128 + tid;
        int i = p >> 5, j = p & 31;
        float dot = 0.0f;
#pragma unroll
        for (int k = 0; k < NDIM; k += 4) {
            float4 a  = *(const float4*)&at[i][k];
            float4 bb = *(const float4*)&at[j][k];
            dot = fmaf(a.x, bb.x, fmaf(a.y, bb.y, fmaf(a.z, bb.z, fmaf(a.w, bb.w, dot))));
        }
        ps += fexp2(fmaf(dot, C2f, -A2f * (anl[i] + anl[j])));
    }
    ps = wred(ps);
    if ((tid & 31) == 0) atomicAdd(&ssum, ps);
    __syncthreads();
    if (tid == 0) g_kyy[c] = ssum * (1.0f / (NK * NK));
}

// ---------------------------------------------------------------------------
// One 128x128 chunk, warp tile 64x32 (ks-outer, R7 form):
// MMA (norms folded into acc init) + fp32 MUFU ex2 epilogue.
// ---------------------------------------------------------------------------
__device__ __forceinline__ float chunk_sum(
    uint32_t Ahi, uint32_t Bb,
    uint32_t aRow, uint32_t bRow, uint32_t klowA, uint32_t klowB, uint32_t mask,
    const float nxr[8], const float cn[8])
{
    float c[4][4][4];
#pragma unroll
    for (int mt = 0; mt < 4; ++mt)
#pragma unroll
        for (int nt = 0; nt < 4; ++nt) {
            c[mt][nt][0] = nxr[mt * 2 + 0] - cn[nt * 2 + 0];
            c[mt][nt][1] = nxr[mt * 2 + 0] - cn[nt * 2 + 1];
            c[mt][nt][2] = nxr[mt * 2 + 1] - cn[nt * 2 + 0];
            c[mt][nt][3] = nxr[mt * 2 + 1] - cn[nt * 2 + 1];
        }

#pragma unroll
    for (int ks = 0; ks < 4; ++ks) {
        const uint32_t colA = ((uint32_t)(ks * 32) + klowA) ^ mask;
        const uint32_t colB = ((uint32_t)(ks * 32) + klowB) ^ mask;
        uint32_t b0[4], b1[4];
        ldsm4(b0, Bb + bRow + colB);            // cols wn*32 .. +15
        ldsm4(b1, Bb + bRow + 2048 + colB);     // cols +16 .. +31
#pragma unroll
        for (int mt = 0; mt < 4; ++mt) {
            uint32_t a[4];
            ldsm4(a, Ahi + aRow + mt * 2048 + colA);
            mma16816(c[mt][0], a, b0 + 0);
            mma16816(c[mt][1], a, b0 + 2);
            mma16816(c[mt][2], a, b1 + 0);
            mma16816(c[mt][3], a, b1 + 2);
        }
    }

    float s0 = 0.f, s1 = 0.f, s2 = 0.f, s3 = 0.f;
#pragma unroll
    for (int mt = 0; mt < 4; ++mt)
#pragma unroll
        for (int nt = 0; nt < 4; ++nt) {
            s0 += mexp2(c[mt][nt][0]);
            s1 += mexp2(c[mt][nt][1]);
            s2 += mexp2(c[mt][nt][2]);
            s3 += mexp2(c[mt][nt][3]);
        }
    return (s0 + s1) + (s2 + s3);
}

// ---------------------------------------------------------------------------
// Main: one CTA per graph. PDL prefix now includes k_xx (prep-independent):
// x-convert + norms + k_xx BEFORE griddepcontrol.wait; prefetch after.
// ---------------------------------------------------------------------------
__global__ void __launch_bounds__(256, 2)
mmd_main(const float* __restrict__ x, float* __restrict__ out)
{
    extern __shared__ char sraw[];
    char* sm = (char*)(((uintptr_t)sraw + 1023) & ~(uintptr_t)1023);
    const uint32_t sb = smem_u32(sm);

    float* xnL = (float*)(sm + OFF_XNL);
    float* red = (float*)(sm + OFF_RED);

    const int tid = threadIdx.x, wid = tid >> 5, l = tid & 31;
    const int b  = blockIdx.x;
    const int wm = wid >> 2;      // row half    -> rows wm*64..+63
    const int wn = wid & 3;       // col quarter -> cols wn*32..+31 = one atom

    if (tid < 65) red[tid] = 0.0f;

    // ---- prefix 1: x tile conversion + norms (prep-independent) ----
    const float4* xg = (const float4*)(x + (size_t)b * NNOD * NDIM);
#pragma unroll
    for (int t = 0; t < 8; ++t) {
        int idx = t * 256 + tid;               // 0..2047 float4
        int row = idx >> 4, k4 = idx & 15;
        float4 v = xg[idx];
        __half h0 = __float2half_rn(v.x * S1f), h1 = __float2half_rn(v.y * S1f);
        __half h2 = __float2half_rn(v.z * S1f), h3 = __float2half_rn(v.w * S1f);
        uint32_t off = sw128((uint32_t)(row * 128 + k4 * 8));
        uint2 ph;
        ph.x = (uint32_t)__half_as_ushort(h0) | ((uint32_t)__half_as_ushort(h1) << 16);
        ph.y = (uint32_t)__half_as_ushort(h2) | ((uint32_t)__half_as_ushort(h3) << 16);
        *(uint2*)(sm + OFF_XHI + off) = ph;
    }
    if (tid < NNOD) {
        const float4* xr4 = (const float4*)(x + ((size_t)b * NNOD + tid) * NDIM);
        float s = 0.0f;
#pragma unroll
        for (int k = 0; k < 16; ++k) {
            float4 v = xr4[k];
            s = fmaf(v.x, v.x, fmaf(v.y, v.y, fmaf(v.z, v.z, fmaf(v.w, v.w, s))));
        }
        xnL[tid] = s * A2f;
    }
    __syncthreads();

    // ---- per-thread ldmatrix address components ----
    const uint32_t mask  = (uint32_t)((l & 7) << 4);
    const uint32_t aRow  = (uint32_t)((wm * 64 + (l & 7) + ((l >> 3) & 1) * 8) * 128);
    const uint32_t klowA = (uint32_t)(((l >> 4) & 1) * 16);
    const uint32_t bRow  = (uint32_t)((wn * 32 + (l & 7) + ((l >> 4) & 1) * 8) * 128);
    const uint32_t klowB = (uint32_t)(((l >> 3) & 1) * 16);
    const uint32_t Ahi   = sb + OFF_XHI;

    // negated row norms: rows wm*64 + mt*16 + (l>>2) + r*8
    float nxr[8];
#pragma unroll
    for (int mt = 0; mt < 4; ++mt) {
        nxr[mt * 2 + 0] = -xnL[wm * 64 + mt * 16 + (l >> 2)];
        nxr[mt * 2 + 1] = -xnL[wm * 64 + mt * 16 + (l >> 2) + 8];
    }

    // ---- prefix 2: k_xx chunk (needs only the x tile — covers prep wait) ----
    {
        float cn[8];
#pragma unroll
        for (int nt = 0; nt < 4; ++nt) {
            cn[nt * 2 + 0] = xnL[wn * 32 + nt * 8 + (l & 3) * 2];
            cn[nt * 2 + 1] = xnL[wn * 32 + nt * 8 + (l & 3) * 2 + 1];
        }
        float s = wred(chunk_sum(Ahi, Ahi, aRow, bRow, klowA, klowB, mask, nxr, cn));
        if (l == 0) atomicAdd(&red[64], s);
    }

    // ---- wait for prep (should be long done), then start atom traffic ----
    GDC_WAIT();
    {
        const uint4* g = (const uint4*)g_at_h;
        uint32_t d = sb + OFF_AT(0);
#pragma unroll
        for (int t = 0; t < 8; ++t) {
            int i = t * 256 + tid;
            cp16(d + i * 16, g + i);
        }
        CP_COMMIT();
    }

    // ---- 8 pairs of atom chunks ----
#pragma unroll 1
    for (int p = 0; p < 8; ++p) {
        __syncthreads();                         // prior pair's reads complete
        if (p < 7) {                             // prefetch chunks 2p+2, 2p+3
            const uint4* g = (const uint4*)g_at_h + (size_t)(2 * p + 2) * 1024;
            uint32_t d = sb + OFF_AT((2 * p + 2) & 3);   // contiguous 32KB pair
#pragma unroll
            for (int t = 0; t < 8; ++t) {
                int i = t * 256 + tid;
                cp16(d + i * 16, g + i);
            }
        }
        CP_COMMIT();
        CP_WAIT1();                              // chunks 2p, 2p+1 landed
        __syncthreads();

#pragma unroll
        for (int h = 0; h < 2; ++h) {
            const int ch = 2 * p + h;
            float cn[8];
#pragma unroll
            for (int nt = 0; nt < 4; ++nt) {
                cn[nt * 2 + 0] = __ldg(&g_anL[ch * 128 + wn * 32 + nt * 8 + (l & 3) * 2]);
                cn[nt * 2 + 1] = __ldg(&g_anL[ch * 128 + wn * 32 + nt * 8 + (l & 3) * 2 + 1]);
            }
            float s = wred(chunk_sum(Ahi, sb + OFF_AT(ch & 3),
                                     aRow, bRow, klowA, klowB, mask, nxr, cn));
            if (l == 0) atomicAdd(&red[ch * 4 + wn], s);
        }
    }

    __syncthreads();
    if (tid < NC) {
        float kxy = red[tid] * (1.0f / (NNOD * NK));
        float kxx = red[64]  * (1.0f / (NNOD * NNOD));
        out[b * NC + tid] = kxx + g_kyy[tid] - 2.0f * kxy;
    }
}

// ---------------------------------------------------------------------------
extern "C" void kernel_launch(void* const* d_in, const int* in_sizes, int n_in,
                              void* d_out, int out_size)
{
    const float* x     = (const float*)d_in[0];
    const float* atoms = (const float*)d_in[1];
    if (n_in >= 2 && in_sizes[0] == CKTOT * NDIM && in_sizes[1] == NBS * NNOD * NDIM) {
        x     = (const float*)d_in[1];
        atoms = (const float*)d_in[0];
    }
    float* out = (float*)d_out;

    cudaFuncSetAttribute(mmd_main, cudaFuncAttributeMaxDynamicSharedMemorySize, SMEM_DYN);

    mmd_prep<<<NC, 128>>>(atoms);

    // main launched with PDL so it starts while prep is still running
    cudaLaunchConfig_t cfg = {};
    cfg.gridDim        = dim3(NBS);
    cfg.blockDim       = dim3(256);
    cfg.dynamicSmemBytes = SMEM_DYN;
    cfg.stream         = 0;
    cudaLaunchAttribute attr[1];
    attr[0].id = cudaLaunchAttributeProgrammaticStreamSerialization;
    attr[0].val.programmaticStreamSerializationAllowed = 1;
    cfg.attrs    = attr;
    cfg.numAttrs = 1;
    cudaLaunchKernelEx(&cfg, mmd_main, x, out);
}